// round 16
// baseline (speedup 1.0000x reference)
#include <cuda_runtime.h>
#include <cstdint>
#include <math.h>

#define K_DIM 128
#define D_DIM 256
#define NTHREADS 512
#define ROWS_PER_CTA 32

__device__ float g_c2[K_DIM];   // ||c_k||^2
__device__ float g_b2[K_DIM];   // 2*||c_k||

__global__ void prep_kernel(const float* __restrict__ C) {
    int k = threadIdx.x;  // 128 threads
    float s = 0.f;
    const float* row = C + (size_t)k * D_DIM;
#pragma unroll 8
    for (int d = 0; d < D_DIM; ++d) s = fmaf(row[d], row[d], s);
    g_c2[k] = s;
    g_b2[k] = 2.0f * sqrtf(s);
}

__device__ __forceinline__ float warp_sum(float p) {
#pragma unroll
    for (int o = 16; o >= 1; o >>= 1) p += __shfl_xor_sync(0xffffffffu, p, o);
    return p;
}
__device__ __forceinline__ float sqrt_apx(float x) {
    float r; asm("sqrt.approx.f32 %0, %1;" : "=f"(r) : "f"(x)); return r;
}

// ---- full per-row argmax given preloaded inputs (warp-collective) ----
__device__ __forceinline__ void compute_row(
    int lane, float4 xa, float4 xb, float4 uu, float4 c2v, float4 b2v,
    const float4* __restrict__ C4, float* __restrict__ orow)
{
    // x2, xn
    float p = xa.x*xa.x + xa.y*xa.y + xa.z*xa.z + xa.w*xa.w
            + xb.x*xb.x + xb.y*xb.y + xb.z*xb.z + xb.w*xb.w;
    const float x2 = warp_sum(p);
    const float xn = sqrt_apx(x2) * 1.00001f + 1e-6f;   // inflated ||x|| upper bound

    // fast gumbel for this lane's 4 k's
    float gq[4];
    gq[0] = -__logf(-__logf(uu.x + 1e-10f) + 1e-10f);
    gq[1] = -__logf(-__logf(uu.y + 1e-10f) + 1e-10f);
    gq[2] = -__logf(-__logf(uu.z + 1e-10f) + 1e-10f);
    gq[3] = -__logf(-__logf(uu.w + 1e-10f) + 1e-10f);

    // upper bounds + packed argmax of (g~ + s_hi)
    float shi[4];
    int pk = 0;   // keys ~[10,30] > 0: int compare monotone; low 7 bits = k
#pragma unroll
    for (int q = 0; q < 4; ++q) {
        float base = x2 + (&c2v.x)[q];
        shi[q] = sqrt_apx(base + xn * (&b2v.x)[q]) + 5e-4f;  // cover approx err
        float key = gq[q] + shi[q];
        int pq = (__float_as_int(key) & ~127) | (lane * 4 + q);
        pk = max(pk, pq);
    }
#pragma unroll
    for (int o = 16; o >= 1; o >>= 1)
        pk = max(pk, __shfl_xor_sync(0xffffffffu, pk, o));
    const int kstar = pk & 127;

    // anchor: exact-dot logit of kstar (approx sqrt; escape re-verifies)
    float4 ca = C4[(size_t)kstar * 64 + lane];
    float4 cb = C4[(size_t)kstar * 64 + 32 + lane];
    float d = fmaf(xa.x, ca.x, fmaf(xa.y, ca.y, fmaf(xa.z, ca.z,
              fmaf(xa.w, ca.w, fmaf(xb.x, cb.x, fmaf(xb.y, cb.y,
              fmaf(xb.z, cb.z, xb.w * cb.w)))))));
    d = warp_sum(d);
    float c2k = __shfl_sync(0xffffffffu, (&c2v.x)[kstar & 3], kstar >> 2);
    float gk0 = __shfl_sync(0xffffffffu, gq[kstar & 3], kstar >> 2);
    float best = sqrt_apx(fmaxf(x2 - 2.f * d + c2k, 0.f)) + gk0;
    float second = -INFINITY;
    int bidx = kstar;

    // candidates vs realized anchor (margin covers fast-log + approx-sqrt + fp)
    unsigned qualm = 0;
#pragma unroll
    for (int q = 0; q < 4; ++q)
        if (gq[q] + shi[q] + 3e-3f >= best && (lane * 4 + q) != kstar)
            qualm |= (1u << q);

    unsigned act = __ballot_sync(0xffffffffu, qualm != 0);
    while (act) {
        int l = __ffs(act) - 1;
        act &= act - 1;
        unsigned qm = __shfl_sync(0xffffffffu, qualm, l);
#pragma unroll
        for (int q = 0; q < 4; ++q) {
            if (qm & (1u << q)) {
                int k = l * 4 + q;
                float4 ka = C4[(size_t)k * 64 + lane];
                float4 kb = C4[(size_t)k * 64 + 32 + lane];
                float dd = fmaf(xa.x, ka.x, fmaf(xa.y, ka.y, fmaf(xa.z, ka.z,
                           fmaf(xa.w, ka.w, fmaf(xb.x, kb.x, fmaf(xb.y, kb.y,
                           fmaf(xb.z, kb.z, xb.w * kb.w)))))));
                dd = warp_sum(dd);
                float c2c = __shfl_sync(0xffffffffu, (&c2v.x)[q], l);
                float gg = __shfl_sync(0xffffffffu, gq[q], l);
                float lg = sqrt_apx(fmaxf(x2 - 2.f * dd + c2c, 0.f)) + gg;
                if (lg > best || (lg == best && k < bidx)) {
                    second = best; best = lg; bidx = k;
                } else if (lg > second) { second = lg; }
            }
        }
    }

    // precision escape: precise sqrtf+logf over candidates + kstar (rare)
    if (best - second < 3e-3f) {
        unsigned qualm2 = qualm;
        if ((kstar >> 2) == lane) qualm2 |= (1u << (kstar & 3));
        best = -INFINITY; second = -INFINITY; bidx = 0;
        unsigned act2 = __ballot_sync(0xffffffffu, qualm2 != 0);
        while (act2) {
            int l = __ffs(act2) - 1;
            act2 &= act2 - 1;
            unsigned qm = __shfl_sync(0xffffffffu, qualm2, l);
#pragma unroll
            for (int q = 0; q < 4; ++q) {
                if (qm & (1u << q)) {
                    int k = l * 4 + q;
                    float4 ka = C4[(size_t)k * 64 + lane];
                    float4 kb = C4[(size_t)k * 64 + 32 + lane];
                    float dd = fmaf(xa.x, ka.x, fmaf(xa.y, ka.y, fmaf(xa.z, ka.z,
                               fmaf(xa.w, ka.w, fmaf(xb.x, kb.x, fmaf(xb.y, kb.y,
                               fmaf(xb.z, kb.z, xb.w * kb.w)))))));
                    dd = warp_sum(dd);
                    float c2c = __shfl_sync(0xffffffffu, (&c2v.x)[q], l);
                    float uk = __shfl_sync(0xffffffffu, (&uu.x)[q], l);
                    float gg = -logf(-logf(uk + 1e-10f) + 1e-10f);
                    float lg = sqrtf(fmaxf(x2 - 2.f * dd + c2c, 0.f)) + gg;
                    if (lg > best || (lg == best && k < bidx)) {
                        second = best; best = lg; bidx = k;
                    } else if (lg > second) { second = lg; }
                }
            }
        }
    }

    // one-hot row (coalesced float4)
    float4 o = make_float4(0.f, 0.f, 0.f, 0.f);
    if ((bidx >> 2) == lane) (&o.x)[bidx & 3] = 1.0f;
    reinterpret_cast<float4*>(orow)[lane] = o;
}

// ---------------- main: 2 rows per warp (batched loads), 512-thread CTAs ----------------
__global__ __launch_bounds__(NTHREADS, 2)
void assign_kernel(const float* __restrict__ seq, const float* __restrict__ u,
                   const float* __restrict__ C, float* __restrict__ assign,
                   int N) {
    const int lane = threadIdx.x & 31;
    const int warp = threadIdx.x >> 5;
    const int row0 = blockIdx.x * ROWS_PER_CTA + warp * 2;
    const int row1 = row0 + 1;
    if (row0 >= N) return;

    const float4* C4 = reinterpret_cast<const float4*>(C);
    float4 c2v = __ldg(&reinterpret_cast<const float4*>(g_c2)[lane]);
    float4 b2v = __ldg(&reinterpret_cast<const float4*>(g_b2)[lane]);

    // issue ALL loads for both rows up front (10 LDG.128 in flight)
    const float4* xr0 = reinterpret_cast<const float4*>(seq + (size_t)row0 * D_DIM);
    float4 xa0 = xr0[lane];
    float4 xb0 = xr0[32 + lane];
    float4 uu0 = reinterpret_cast<const float4*>(u + (size_t)row0 * K_DIM)[lane];

    const bool has1 = (row1 < N);
    const float4* xr1 = reinterpret_cast<const float4*>(seq + (size_t)(has1 ? row1 : row0) * D_DIM);
    float4 xa1 = xr1[lane];
    float4 xb1 = xr1[32 + lane];
    float4 uu1 = reinterpret_cast<const float4*>(u + (size_t)(has1 ? row1 : row0) * K_DIM)[lane];

    compute_row(lane, xa0, xb0, uu0, c2v, b2v, C4, assign + (size_t)row0 * K_DIM);
    if (has1)
        compute_row(lane, xa1, xb1, uu1, c2v, b2v, C4, assign + (size_t)row1 * K_DIM);
}

extern "C" void kernel_launch(void* const* d_in, const int* in_sizes, int n_in,
                              void* d_out, int out_size) {
    const float* seq = (const float*)d_in[0];  // [N,256]
    const float* u   = (const float*)d_in[1];  // [N,128]
    const float* C   = (const float*)d_in[2];  // [128,256]

    const int N = in_sizes[1] / K_DIM;
    float* out = (float*)d_out;
    float* assign = out;

    long long need_both = (long long)N * K_DIM + (long long)K_DIM * D_DIM;
    if ((long long)out_size >= need_both) {
        cudaMemcpyAsync(out, C, (size_t)K_DIM * D_DIM * sizeof(float),
                        cudaMemcpyDeviceToDevice);
        assign = out + K_DIM * D_DIM;
    }

    prep_kernel<<<1, K_DIM>>>(C);

    int grid = (N + ROWS_PER_CTA - 1) / ROWS_PER_CTA;
    assign_kernel<<<grid, NTHREADS>>>(seq, u, C, assign, N);
}

// round 17
// speedup vs baseline: 1.2143x; 1.2143x over previous
#include <cuda_runtime.h>
#include <cstdint>
#include <math.h>

#define K_DIM 128
#define D_DIM 256
#define NTHREADS 256
#define ROWS_PER_CTA 8

__device__ float g_c2[K_DIM];   // ||c_k||^2
__device__ float g_b2[K_DIM];   // 2*||c_k||

// ---------------- prep: c2 + b2 ----------------
__global__ void prep_kernel(const float* __restrict__ C) {
    int k = threadIdx.x;  // 128 threads
    float s = 0.f;
    const float* row = C + (size_t)k * D_DIM;
#pragma unroll 8
    for (int d = 0; d < D_DIM; ++d) s = fmaf(row[d], row[d], s);
    g_c2[k] = s;
    g_b2[k] = 2.0f * sqrtf(s);
}

__device__ __forceinline__ float warp_sum(float p) {
#pragma unroll
    for (int o = 16; o >= 1; o >>= 1) p += __shfl_xor_sync(0xffffffffu, p, o);
    return p;
}
__device__ __forceinline__ float sqrt_apx(float x) {
    float r; asm("sqrt.approx.f32 %0, %1;" : "=f"(r) : "f"(x)); return r;
}

// ---------------- main: one warp per row, anchor-pruned argmax ----------------
__global__ __launch_bounds__(NTHREADS)
void assign_kernel(const float* __restrict__ seq, const float* __restrict__ u,
                   const float* __restrict__ C, float* __restrict__ assign,
                   int N) {
    const int lane = threadIdx.x & 31;
    const int row = blockIdx.x * ROWS_PER_CTA + (threadIdx.x >> 5);
    if (row >= N) return;

    // ---- coalesced loads: x row (2 float4/lane), u row, c2/b2 (L1-hot) ----
    const float4* xr = reinterpret_cast<const float4*>(seq + (size_t)row * D_DIM);
    float4 xa = xr[lane];
    float4 xb = xr[32 + lane];
    float4 uu = reinterpret_cast<const float4*>(u + (size_t)row * K_DIM)[lane];
    float4 c2v = __ldg(&reinterpret_cast<const float4*>(g_c2)[lane]);
    float4 b2v = __ldg(&reinterpret_cast<const float4*>(g_b2)[lane]);

    // ---- x2, xn ----
    float p = xa.x*xa.x + xa.y*xa.y + xa.z*xa.z + xa.w*xa.w
            + xb.x*xb.x + xb.y*xb.y + xb.z*xb.z + xb.w*xb.w;
    const float x2 = warp_sum(p);
    const float xn = sqrt_apx(x2) * 1.00001f + 1e-6f;   // inflated ||x|| upper bound

    // ---- fast gumbel for this lane's 4 k's ----
    float gq[4];
    gq[0] = -__logf(-__logf(uu.x + 1e-10f) + 1e-10f);
    gq[1] = -__logf(-__logf(uu.y + 1e-10f) + 1e-10f);
    gq[2] = -__logf(-__logf(uu.z + 1e-10f) + 1e-10f);
    gq[3] = -__logf(-__logf(uu.w + 1e-10f) + 1e-10f);

    // ---- upper bounds + packed argmax of (g~ + s_hi) ----
    float shi[4];
    int pk = 0;   // keys ~[10,30] > 0: int compare monotone; low 7 bits carry k
#pragma unroll
    for (int q = 0; q < 4; ++q) {
        float base = x2 + (&c2v.x)[q];
        shi[q] = sqrt_apx(base + xn * (&b2v.x)[q]) + 5e-4f;  // cover approx err
        float key = gq[q] + shi[q];
        int pq = (__float_as_int(key) & ~127) | (lane * 4 + q);
        pk = max(pk, pq);
    }
#pragma unroll
    for (int o = 16; o >= 1; o >>= 1)
        pk = max(pk, __shfl_xor_sync(0xffffffffu, pk, o));
    const int kstar = pk & 127;

    const float4* C4 = reinterpret_cast<const float4*>(C);

    // ---- anchor: exact-dot logit of kstar (approx sqrt; escape re-verifies) ----
    float4 ca = C4[(size_t)kstar * 64 + lane];
    float4 cb = C4[(size_t)kstar * 64 + 32 + lane];
    float d = fmaf(xa.x, ca.x, fmaf(xa.y, ca.y, fmaf(xa.z, ca.z,
              fmaf(xa.w, ca.w, fmaf(xb.x, cb.x, fmaf(xb.y, cb.y,
              fmaf(xb.z, cb.z, xb.w * cb.w)))))));
    d = warp_sum(d);
    float c2k = __shfl_sync(0xffffffffu, (&c2v.x)[kstar & 3], kstar >> 2);
    float gk0 = __shfl_sync(0xffffffffu, gq[kstar & 3], kstar >> 2);
    float best = sqrt_apx(fmaxf(x2 - 2.f * d + c2k, 0.f)) + gk0;
    float second = -INFINITY;
    int bidx = kstar;

    // ---- candidates vs realized anchor (margin covers fast-log + approx-sqrt + fp) ----
    unsigned qualm = 0;
#pragma unroll
    for (int q = 0; q < 4; ++q)
        if (gq[q] + shi[q] + 3e-3f >= best && (lane * 4 + q) != kstar)
            qualm |= (1u << q);

    unsigned act = __ballot_sync(0xffffffffu, qualm != 0);
    while (act) {
        int l = __ffs(act) - 1;
        act &= act - 1;
        unsigned qm = __shfl_sync(0xffffffffu, qualm, l);
#pragma unroll
        for (int q = 0; q < 4; ++q) {
            if (qm & (1u << q)) {
                int k = l * 4 + q;
                float4 ka = C4[(size_t)k * 64 + lane];
                float4 kb = C4[(size_t)k * 64 + 32 + lane];
                float dd = fmaf(xa.x, ka.x, fmaf(xa.y, ka.y, fmaf(xa.z, ka.z,
                           fmaf(xa.w, ka.w, fmaf(xb.x, kb.x, fmaf(xb.y, kb.y,
                           fmaf(xb.z, kb.z, xb.w * kb.w)))))));
                dd = warp_sum(dd);
                float c2c = __shfl_sync(0xffffffffu, (&c2v.x)[q], l);
                float gg = __shfl_sync(0xffffffffu, gq[q], l);
                float lg = sqrt_apx(fmaxf(x2 - 2.f * dd + c2c, 0.f)) + gg;
                if (lg > best || (lg == best && k < bidx)) {
                    second = best; best = lg; bidx = k;
                } else if (lg > second) { second = lg; }
            }
        }
    }

    // ---- precision escape: precise sqrtf+logf over candidates + kstar (rare) ----
    if (best - second < 3e-3f) {
        unsigned qualm2 = qualm;
        if ((kstar >> 2) == lane) qualm2 |= (1u << (kstar & 3));
        best = -INFINITY; second = -INFINITY; bidx = 0;
        unsigned act2 = __ballot_sync(0xffffffffu, qualm2 != 0);
        while (act2) {
            int l = __ffs(act2) - 1;
            act2 &= act2 - 1;
            unsigned qm = __shfl_sync(0xffffffffu, qualm2, l);
#pragma unroll
            for (int q = 0; q < 4; ++q) {
                if (qm & (1u << q)) {
                    int k = l * 4 + q;
                    float4 ka = C4[(size_t)k * 64 + lane];
                    float4 kb = C4[(size_t)k * 64 + 32 + lane];
                    float dd = fmaf(xa.x, ka.x, fmaf(xa.y, ka.y, fmaf(xa.z, ka.z,
                               fmaf(xa.w, ka.w, fmaf(xb.x, kb.x, fmaf(xb.y, kb.y,
                               fmaf(xb.z, kb.z, xb.w * kb.w)))))));
                    dd = warp_sum(dd);
                    float c2c = __shfl_sync(0xffffffffu, (&c2v.x)[q], l);
                    float uk = __shfl_sync(0xffffffffu, (&uu.x)[q], l);
                    float gg = -logf(-logf(uk + 1e-10f) + 1e-10f);
                    float lg = sqrtf(fmaxf(x2 - 2.f * dd + c2c, 0.f)) + gg;
                    if (lg > best || (lg == best && k < bidx)) {
                        second = best; best = lg; bidx = k;
                    } else if (lg > second) { second = lg; }
                }
            }
        }
    }

    // ---- one-hot row (coalesced float4) ----
    float4 o = make_float4(0.f, 0.f, 0.f, 0.f);
    if ((bidx >> 2) == lane) (&o.x)[bidx & 3] = 1.0f;
    reinterpret_cast<float4*>(assign + (size_t)row * K_DIM)[lane] = o;
}

extern "C" void kernel_launch(void* const* d_in, const int* in_sizes, int n_in,
                              void* d_out, int out_size) {
    const float* seq = (const float*)d_in[0];  // [N,256]
    const float* u   = (const float*)d_in[1];  // [N,128]
    const float* C   = (const float*)d_in[2];  // [128,256]

    const int N = in_sizes[1] / K_DIM;
    float* out = (float*)d_out;
    float* assign = out;

    long long need_both = (long long)N * K_DIM + (long long)K_DIM * D_DIM;
    if ((long long)out_size >= need_both) {
        cudaMemcpyAsync(out, C, (size_t)K_DIM * D_DIM * sizeof(float),
                        cudaMemcpyDeviceToDevice);
        assign = out + K_DIM * D_DIM;
    }

    prep_kernel<<<1, K_DIM>>>(C);

    int grid = (N + ROWS_PER_CTA - 1) / ROWS_PER_CTA;
    assign_kernel<<<grid, NTHREADS>>>(seq, u, C, assign, N);
}